// round 1
// baseline (speedup 1.0000x reference)
#include <cuda_runtime.h>

#define K_H  128
#define K_W  128
#define K_HW (K_H*K_W)
#define K_B  4
#define K_NS 33

// ---------------- static scratch (no runtime allocation) ----------------
__device__ float g_gbuf[64*K_HW];              // relu(coord conv) feats, batch-independent
__device__ float g_Wp1[9*576*256];             // repacked [kidx][ci][co]
__device__ float g_Wp2[9*256*128];
__device__ float g_Wp3[9*128*64];
__device__ float g_y1[(size_t)K_B*256*K_HW];   // raw conv outputs (pre-GN)
__device__ float g_y2[(size_t)K_B*128*K_HW];
__device__ float g_y3[(size_t)K_B*64*K_HW];
__device__ float g_gs[3][64];                  // per-(b,group) sums   (max B*8=32 used)
__device__ float g_gq[3][64];                  // per-(b,group) sumsq
__device__ float g_sct1[K_B*256*2];            // per-(b,c) GN scale/shift
__device__ float g_sct2[K_B*128*2];
__device__ float g_sct3[K_B*64*2];
__device__ float g_psum[K_B*K_NS*64];          // segment sums
__device__ float g_pcnt[K_B*K_NS];             // segment counts

// ---------------- small utility kernels ----------------
__global__ void zero_bufs(){
    int i = blockIdx.x*256 + threadIdx.x;
    if (i < K_B*K_NS*64) g_psum[i] = 0.f;
    if (i < K_B*K_NS)    g_pcnt[i] = 0.f;
    if (i < 64){
        g_gs[0][i]=0.f; g_gs[1][i]=0.f; g_gs[2][i]=0.f;
        g_gq[0][i]=0.f; g_gq[1][i]=0.f; g_gq[2][i]=0.f;
    }
}

template<int LAYER>
__global__ void repack_w(const float* __restrict__ w){
    constexpr int Cin  = (LAYER==1)?576:(LAYER==2)?256:128;
    constexpr int Cout = (LAYER==1)?256:(LAYER==2)?128:64;
    float* wp = (LAYER==1)?g_Wp1:(LAYER==2)?g_Wp2:g_Wp3;
    int n = Cout*Cin*9;
    for (int i = blockIdx.x*blockDim.x + threadIdx.x; i < n; i += gridDim.x*blockDim.x){
        int k  = i % 9;
        int t  = i / 9;
        int ci = t % Cin;
        int co = t / Cin;
        wp[(k*Cin + ci)*Cout + co] = w[i];
    }
}

// grid feats: relu(wc0*gx + wc1*gy + b) ; gx = w index, gy = h index
__global__ void grid_feats(const float* __restrict__ wc, const float* __restrict__ bc){
    int i = blockIdx.x*blockDim.x + threadIdx.x;
    if (i >= 64*K_HW) return;
    int c = i / K_HW, p = i % K_HW;
    int hy = p / K_W, wx = p % K_W;
    float v = wc[2*c]*(float)wx + wc[2*c+1]*(float)hy + bc[c];
    g_gbuf[i] = fmaxf(v, 0.f);
}

// ---------------- conv3x3 as 9 shifted GEMMs ----------------
// tile: BM(co) x 128(px = full image row) x BK(ci) ; thread tile COF x 8
// LAYER 1: input = concat(x, g_gbuf), identity transform
// LAYER 2/3: input = relu(s*y_prev + t) with per-(b,c) GN affine, zero-padded
template<int LAYER>
__global__ void __launch_bounds__(256, 2)
conv3x3(const float* __restrict__ xin, const float* __restrict__ bias){
    constexpr int Cin  = (LAYER==1)?576:(LAYER==2)?256:128;
    constexpr int Cout = (LAYER==1)?256:(LAYER==2)?128:64;
    constexpr int COF  = (LAYER==3)?4:8;
    constexpr int BM   = COF*16;
    constexpr int BK   = 8;
    constexpr int AE   = BK*BM/256;
    constexpr int nCb  = Cin/BK;
    constexpr int nCh  = 9*nCb;

    const float* __restrict__ wp  = (LAYER==1)?g_Wp1:(LAYER==2)?g_Wp2:g_Wp3;
    const float* __restrict__ in  = (LAYER==1)?xin:(LAYER==2)?g_y1:g_y2;
    const float* __restrict__ sct = (LAYER==2)?g_sct1:g_sct2;  // unused for LAYER==1
    float* __restrict__ out       = (LAYER==1)?g_y1:(LAYER==2)?g_y2:g_y3;

    const int h   = blockIdx.x;
    const int b   = blockIdx.y;
    const int cob = blockIdx.z*BM;
    const int tid = threadIdx.x;
    const int tx  = tid & 15, ty = tid >> 4;
    const int brow = tid >> 5;        // 0..7 : ci row within chunk
    const int lane = tid & 31;

    __shared__ __align__(16) float As[2][BK][BM];
    __shared__ __align__(16) float Bs[2][BK][128];

    float acc[COF][8];
    #pragma unroll
    for (int i=0;i<COF;i++)
        #pragma unroll
        for (int j=0;j<8;j++) acc[i][j]=0.f;

    float rA[AE], rB[4];

#define LOADC(CC) { \
        const int k_  = (CC)/nCb; \
        const int cb_ = (CC) - k_*nCb; \
        const int ky_ = k_/3 - 1, kx_ = (k_%3) - 1; \
        const int hh_ = h + ky_; \
        const bool rok_ = (hh_>=0) && (hh_<K_H); \
        for (int e=0;e<AE;e++){ \
            int idx = e*256 + tid; int r_ = idx/BM; int cl_ = idx - r_*BM; \
            rA[e] = wp[(size_t)(k_*Cin + cb_*BK + r_)*Cout + cob + cl_]; \
        } \
        const int ci_ = cb_*BK + brow; \
        if (LAYER==1){ \
            const float* src_ = (ci_<512) ? (xin + ((size_t)(b*512+ci_)*K_H + hh_)*K_W) \
                                          : (g_gbuf + ((size_t)(ci_-512)*K_H + hh_)*K_W); \
            for (int j=0;j<4;j++){ \
                int sc_ = lane + j*32 + kx_; \
                rB[j] = (rok_ && sc_>=0 && sc_<K_W) ? src_[sc_] : 0.f; \
            } \
        } else { \
            float s_ = sct[(b*Cin+ci_)*2], t_ = sct[(b*Cin+ci_)*2+1]; \
            const float* src_ = in + ((size_t)(b*Cin+ci_)*K_H + hh_)*K_W; \
            for (int j=0;j<4;j++){ \
                int sc_ = lane + j*32 + kx_; \
                rB[j] = (rok_ && sc_>=0 && sc_<K_W) ? fmaxf(fmaf(s_, src_[sc_], t_), 0.f) : 0.f; \
            } \
        } \
    }

#define STOREC(BI) { \
        for (int e=0;e<AE;e++){ \
            int idx = e*256 + tid; int r_ = idx/BM; int cl_ = idx - r_*BM; \
            As[BI][r_][cl_] = rA[e]; \
        } \
        for (int j=0;j<4;j++) Bs[BI][brow][lane + j*32] = rB[j]; \
    }

    LOADC(0);
    STOREC(0);
    __syncthreads();
    int buf = 0;

    for (int cc = 0; cc < nCh; ++cc){
        if (cc+1 < nCh) LOADC(cc+1);

        #pragma unroll
        for (int k=0;k<BK;k++){
            float av[COF], bv[8];
            #pragma unroll
            for (int i=0;i<COF/2;i++){
                av[i]         = As[buf][k][ty*(COF/2)+i];
                av[i+COF/2]   = As[buf][k][BM/2 + ty*(COF/2)+i];
            }
            float4 b0 = *(const float4*)&Bs[buf][k][tx*4];
            float4 b1 = *(const float4*)&Bs[buf][k][64 + tx*4];
            bv[0]=b0.x; bv[1]=b0.y; bv[2]=b0.z; bv[3]=b0.w;
            bv[4]=b1.x; bv[5]=b1.y; bv[6]=b1.z; bv[7]=b1.w;
            #pragma unroll
            for (int i=0;i<COF;i++)
                #pragma unroll
                for (int j=0;j<8;j++)
                    acc[i][j] = fmaf(av[i], bv[j], acc[i][j]);
        }

        if (cc+1 < nCh){
            STOREC(buf^1);
            __syncthreads();
            buf ^= 1;
        }
    }
#undef LOADC
#undef STOREC

    #pragma unroll
    for (int i=0;i<COF;i++){
        int coff = (i < COF/2) ? (ty*(COF/2)+i) : (BM/2 + ty*(COF/2) + (i - COF/2));
        int co = cob + coff;
        float bvv = bias[co];
        float* orow = out + ((size_t)(b*Cout+co)*K_H + h)*K_W;
        float4 v0 = make_float4(acc[i][0]+bvv, acc[i][1]+bvv, acc[i][2]+bvv, acc[i][3]+bvv);
        float4 v1 = make_float4(acc[i][4]+bvv, acc[i][5]+bvv, acc[i][6]+bvv, acc[i][7]+bvv);
        *(float4*)(orow + tx*4)      = v0;
        *(float4*)(orow + 64 + tx*4) = v1;
    }
}

// ---------------- GroupNorm: stats + finalize ----------------
template<int LAYER>
__global__ void gn_stats(){
    constexpr int C  = (LAYER==1)?256:(LAYER==2)?128:64;
    constexpr int Cg = (LAYER==3)?16:32;
    const float* y = (LAYER==1)?g_y1:(LAYER==2)?g_y2:g_y3;
    int bc = blockIdx.x;                      // b*C + c
    const float* p = y + (size_t)bc*K_HW;
    float s = 0.f, q = 0.f;
    for (int i = threadIdx.x; i < K_HW; i += 256){
        float v = p[i]; s += v; q = fmaf(v, v, q);
    }
    #pragma unroll
    for (int o=16;o;o>>=1){
        s += __shfl_down_sync(0xffffffffu, s, o);
        q += __shfl_down_sync(0xffffffffu, q, o);
    }
    __shared__ float ss[8], sq[8];
    int wid = threadIdx.x >> 5, ln = threadIdx.x & 31;
    if (ln == 0){ ss[wid] = s; sq[wid] = q; }
    __syncthreads();
    if (threadIdx.x == 0){
        s = 0.f; q = 0.f;
        #pragma unroll
        for (int i=0;i<8;i++){ s += ss[i]; q += sq[i]; }
        int b = bc / C, c = bc % C;
        int g = b*(C/Cg) + c/Cg;
        atomicAdd(&g_gs[LAYER-1][g], s);
        atomicAdd(&g_gq[LAYER-1][g], q);
    }
}

template<int LAYER>
__global__ void gn_fin(const float* __restrict__ gamma, const float* __restrict__ beta){
    constexpr int C  = (LAYER==1)?256:(LAYER==2)?128:64;
    constexpr int Cg = (LAYER==3)?16:32;
    float* sct = (LAYER==1)?g_sct1:(LAYER==2)?g_sct2:g_sct3;
    int i = blockIdx.x*blockDim.x + threadIdx.x;
    if (i >= K_B*C) return;
    int b = i / C, c = i % C;
    int g = b*(C/Cg) + c/Cg;
    float n   = (float)Cg * (float)K_HW;
    float mu  = g_gs[LAYER-1][g] / n;
    float var = g_gq[LAYER-1][g] / n - mu*mu;
    float inv = rsqrtf(var + 1e-5f);
    float s = gamma[c]*inv;
    sct[2*i]   = s;
    sct[2*i+1] = beta[c] - mu*s;
}

// ---------------- segment pooling (GN3+relu fused on load) ----------------
__global__ void pool_seg(const int* __restrict__ masks){
    __shared__ float sacc[K_NS][64];
    __shared__ float scnt[K_NS];
    __shared__ int   smask[1024];
    int b     = blockIdx.y;
    int pbase = blockIdx.x*1024;
    int tid   = threadIdx.x;
    for (int i=tid;i<K_NS*64;i+=256) (&sacc[0][0])[i] = 0.f;
    if (tid < K_NS) scnt[tid] = 0.f;
    for (int i=tid;i<1024;i+=256) smask[i] = masks[b*K_HW + pbase + i];
    __syncthreads();

    int c   = tid & 63;
    int grp = tid >> 6;                       // 4 pixel groups of 256
    float s = g_sct3[(b*64+c)*2], t = g_sct3[(b*64+c)*2+1];
    const float* yrow = g_y3 + (size_t)(b*64+c)*K_HW + pbase + grp*256;
    const int*   mrow = smask + grp*256;
    for (int pp=0; pp<256; ++pp){
        int seg = mrow[pp];
        float v = fmaxf(fmaf(s, yrow[pp], t), 0.f);
        atomicAdd(&sacc[seg][c], v);
        if (c == 0) atomicAdd(&scnt[seg], 1.f);
    }
    __syncthreads();
    for (int i=tid;i<K_NS*64;i+=256) atomicAdd(&g_psum[b*K_NS*64 + i], (&sacc[0][0])[i]);
    if (tid < K_NS) atomicAdd(&g_pcnt[b*K_NS + tid], scnt[tid]);
}

// ---------------- heads: boxes [B,32,7] then scores [B,32] ----------------
__global__ void heads(const float* __restrict__ wbox, const float* __restrict__ bbox,
                      const float* __restrict__ wconf, const float* __restrict__ bconf,
                      float* __restrict__ outp){
    int t = threadIdx.x;
    if (t >= K_B*32) return;
    int b = t / 32, o = t % 32, s = o + 1;
    float inv = 1.f / fmaxf(g_pcnt[b*K_NS + s], 1e-4f);
    const float* ps = &g_psum[(b*K_NS + s)*64];
    float pooled[64];
    #pragma unroll
    for (int c=0;c<64;c++) pooled[c] = ps[c]*inv;
    #pragma unroll
    for (int k=0;k<7;k++){
        float d = bbox[k];
        #pragma unroll
        for (int c=0;c<64;c++) d = fmaf(pooled[c], wbox[k*64+c], d);
        outp[(b*32 + o)*7 + k] = d;
    }
    float d = bconf[0];
    #pragma unroll
    for (int c=0;c<64;c++) d = fmaf(pooled[c], wconf[c], d);
    outp[K_B*32*7 + b*32 + o] = d;
}

// ---------------- launch ----------------
extern "C" void kernel_launch(void* const* d_in, const int* in_sizes, int n_in,
                              void* d_out, int out_size){
    const float* x      = (const float*)d_in[0];
    const int*   masks  = (const int*)  d_in[1];
    const float* wcoord = (const float*)d_in[2];
    const float* bcoord = (const float*)d_in[3];
    const float* w1     = (const float*)d_in[4];
    const float* b1     = (const float*)d_in[5];
    const float* gm1    = (const float*)d_in[6];
    const float* bt1    = (const float*)d_in[7];
    const float* w2     = (const float*)d_in[8];
    const float* b2     = (const float*)d_in[9];
    const float* gm2    = (const float*)d_in[10];
    const float* bt2    = (const float*)d_in[11];
    const float* w3     = (const float*)d_in[12];
    const float* b3     = (const float*)d_in[13];
    const float* gm3    = (const float*)d_in[14];
    const float* bt3    = (const float*)d_in[15];
    const float* wbox   = (const float*)d_in[16];
    const float* bbox   = (const float*)d_in[17];
    const float* wconf  = (const float*)d_in[18];
    const float* bconf  = (const float*)d_in[19];
    float* outp = (float*)d_out;

    zero_bufs<<<33,256>>>();
    repack_w<1><<<512,256>>>(w1);
    repack_w<2><<<256,256>>>(w2);
    repack_w<3><<<128,256>>>(w3);
    grid_feats<<<(64*K_HW+255)/256,256>>>(wcoord, bcoord);

    { dim3 g(K_H, K_B, 2); conv3x3<1><<<g,256>>>(x, b1); }
    gn_stats<1><<<K_B*256,256>>>();
    gn_fin<1><<<(K_B*256+255)/256,256>>>(gm1, bt1);

    { dim3 g(K_H, K_B, 1); conv3x3<2><<<g,256>>>(x, b2); }
    gn_stats<2><<<K_B*128,256>>>();
    gn_fin<2><<<(K_B*128+255)/256,256>>>(gm2, bt2);

    { dim3 g(K_H, K_B, 1); conv3x3<3><<<g,256>>>(x, b3); }
    gn_stats<3><<<K_B*64,256>>>();
    gn_fin<3><<<1,256>>>(gm3, bt3);

    { dim3 g(16, K_B); pool_seg<<<g,256>>>(masks); }
    heads<<<1,128>>>(wbox, bbox, wconf, bconf, outp);
}

// round 3
// speedup vs baseline: 2.4091x; 2.4091x over previous
#include <cuda_runtime.h>
#include <cuda_bf16.h>
#include <cstdint>

#define K_H  128
#define K_W  128
#define K_HW 16384
#define K_B  4
#define K_NS 33

// ======================= device scratch (static, no alloc) =======================
__device__ __align__(16) uint32_t g_a1[(size_t)K_B*K_HW*576];   // conv1 in, NHWC packed(hi,lo)
__device__ __align__(16) uint32_t g_a2[(size_t)K_B*K_HW*256];   // conv2 in
__device__ __align__(16) uint32_t g_a3[(size_t)K_B*K_HW*128];   // conv3 in
__device__ __align__(16) float    g_y1[(size_t)K_B*K_HW*256];   // conv outs, fp32 NHWC (pre-GN)
__device__ __align__(16) float    g_y2[(size_t)K_B*K_HW*128];
__device__ __align__(16) float    g_y3[(size_t)K_B*K_HW*64];
__device__ __align__(16) uint32_t g_w1[9*256*576];              // weights [k][co][ci] packed(hi,lo)
__device__ __align__(16) uint32_t g_w2[9*128*256];
__device__ __align__(16) uint32_t g_w3[9*64*128];
__device__ float g_gs[3][64], g_gq[3][64];
__device__ float g_sct1[K_B*256*2], g_sct2[K_B*128*2], g_sct3[K_B*64*2];
__device__ float g_psum[K_B*K_NS*64];
__device__ float g_pcnt[K_B*K_NS];

// ======================= helpers =======================
__device__ __forceinline__ uint32_t smem_u32(const void* p) {
    uint32_t a;
    asm("{ .reg .u64 t; cvta.to.shared.u64 t, %1; cvt.u32.u64 %0, t; }" : "=r"(a) : "l"(p));
    return a;
}
__device__ __forceinline__ void sts64(uint32_t addr, uint32_t a, uint32_t b){
    asm volatile("st.shared.v2.u32 [%0], {%1,%2};" :: "r"(addr), "r"(a), "r"(b));
}
__device__ __forceinline__ void ldsm4(uint32_t (&r)[4], uint32_t a){
    asm volatile("ldmatrix.sync.aligned.m8n8.x4.shared.b16 {%0,%1,%2,%3}, [%4];"
        : "=r"(r[0]), "=r"(r[1]), "=r"(r[2]), "=r"(r[3]) : "r"(a));
}
__device__ __forceinline__ void mma16816(float (&d)[4], const uint32_t (&a)[4],
                                         uint32_t b0, uint32_t b1){
    asm volatile(
        "mma.sync.aligned.m16n8k16.row.col.f32.bf16.bf16.f32 "
        "{%0,%1,%2,%3},{%4,%5,%6,%7},{%8,%9},{%0,%1,%2,%3};"
        : "+f"(d[0]), "+f"(d[1]), "+f"(d[2]), "+f"(d[3])
        : "r"(a[0]), "r"(a[1]), "r"(a[2]), "r"(a[3]), "r"(b0), "r"(b1));
}
// hi/lo bf16 split pack
__device__ __forceinline__ uint32_t pack_hl(float v){
    __nv_bfloat16 h = __float2bfloat16(v);
    float hf = __bfloat162float(h);
    __nv_bfloat16 l = __float2bfloat16(v - hf);
    return (uint32_t)__bfloat16_as_ushort(h) | ((uint32_t)__bfloat16_as_ushort(l) << 16);
}

// ======================= small kernels =======================
__global__ void zero_bufs(){
    int i = blockIdx.x*256 + threadIdx.x;
    if (i < K_B*K_NS*64) g_psum[i] = 0.f;
    if (i < K_B*K_NS)    g_pcnt[i] = 0.f;
    if (i < 64){
        g_gs[0][i]=0.f; g_gs[1][i]=0.f; g_gs[2][i]=0.f;
        g_gq[0][i]=0.f; g_gq[1][i]=0.f; g_gq[2][i]=0.f;
    }
}

template<int LAYER>
__global__ void repack_w(const float* __restrict__ w){
    constexpr int Cin  = (LAYER==1)?576:(LAYER==2)?256:128;
    constexpr int Cout = (LAYER==1)?256:(LAYER==2)?128:64;
    uint32_t* wp = (LAYER==1)?g_w1:(LAYER==2)?g_w2:g_w3;
    int n = Cout*Cin*9;
    for (int i = blockIdx.x*blockDim.x + threadIdx.x; i < n; i += gridDim.x*blockDim.x){
        int k  = i % 9;
        int t  = i / 9;
        int ci = t % Cin;
        int co = t / Cin;
        wp[((size_t)k*Cout + co)*Cin + ci] = pack_hl(w[i]);
    }
}

// conv1 input: NCHW fp32 (+ computed coord feats 512..575) -> NHWC packed hi/lo
__global__ void xform1(const float* __restrict__ x, const float* __restrict__ wc,
                       const float* __restrict__ bc){
    __shared__ float tile[64][129];
    int cblk = blockIdx.x, h = blockIdx.y, b = blockIdx.z, tid = threadIdx.x;
    if (cblk < 8){
        for (int i = tid; i < 64*128; i += 256){
            int ci = i >> 7, w = i & 127;
            tile[ci][w] = x[(((size_t)b*512 + cblk*64 + ci)*K_H + h)*K_W + w];
        }
    } else {
        for (int i = tid; i < 64*128; i += 256){
            int ci = i >> 7, w = i & 127;
            tile[ci][w] = fmaxf(wc[2*ci]*(float)w + wc[2*ci+1]*(float)h + bc[ci], 0.f);
        }
    }
    __syncthreads();
    for (int i = tid; i < 64*128; i += 256){
        int px = i >> 6, c = i & 63;
        g_a1[(((size_t)b*K_H + h)*K_W + px)*576 + cblk*64 + c] = pack_hl(tile[c][px]);
    }
}

// GN apply + relu + split-pack (fp32 NHWC -> packed NHWC) ; L=2: y1->a2, L=3: y2->a3
template<int L>
__global__ void act_xform(){
    constexpr int C = (L==2)?256:128;
    const float* __restrict__ y   = (L==2)?g_y1:g_y2;
    const float* __restrict__ sct = (L==2)?g_sct1:g_sct2;
    uint32_t* __restrict__ a      = (L==2)?g_a2:g_a3;
    size_t idx = (size_t)blockIdx.x*256 + threadIdx.x;
    if (idx >= (size_t)K_B*K_HW*C) return;
    int c = (int)(idx % C);
    int b = (int)(idx / ((size_t)K_HW*C));
    float2 st = ((const float2*)sct)[b*C + c];
    float v = fmaxf(fmaf(st.x, y[idx], st.y), 0.f);
    a[idx] = pack_hl(v);
}

// ======================= conv3x3 via mma.sync bf16x3 =======================
// CTA: M=128 px (one row) x N=BN cout ; 8 warps = 4(M) x 2(N); warp tile 32 x BN/2
// K chunks of 32 ci over 9 kernel positions.
template<int LAYER>
__global__ void __launch_bounds__(256, 1)
conv_hmma(const float* __restrict__ bias){
    constexpr int Cin  = (LAYER==1)?576:(LAYER==2)?256:128;
    constexpr int Cout = (LAYER==1)?256:(LAYER==2)?128:64;
    constexpr int BN   = (Cout>=128)?128:64;
    constexpr int NCB  = Cin/32;
    constexpr int NC   = 9*NCB;
    constexpr int NI   = BN/16;            // 8x-wide n-tiles per warp (8 or 4)
    constexpr int B_IT = BN/32;            // uint4 B loads per thread (4 or 2)
    constexpr int ASZ  = 128*80;           // one A plane (hi or lo)
    constexpr int BSZ  = BN*80;            // one B plane
    constexpr int BUF  = 2*ASZ + 2*BSZ;

    const uint32_t* __restrict__ act = (LAYER==1)?g_a1:(LAYER==2)?g_a2:g_a3;
    const uint32_t* __restrict__ wp  = (LAYER==1)?g_w1:(LAYER==2)?g_w2:g_w3;
    float* __restrict__ out          = (LAYER==1)?g_y1:(LAYER==2)?g_y2:g_y3;

    extern __shared__ __align__(16) char dsm[];
    const uint32_t sbase = smem_u32(dsm);

    const int tid  = threadIdx.x;
    const int lane = tid & 31;
    const int wm   = (tid >> 5) & 3;
    const int wn   = tid >> 7;
    const int h    = blockIdx.x;
    const int b    = blockIdx.y;
    const int cob  = blockIdx.z*BN;

    float acc[2][NI][4];
    #pragma unroll
    for (int mi=0;mi<2;mi++)
        #pragma unroll
        for (int ni=0;ni<NI;ni++)
            #pragma unroll
            for (int j=0;j<4;j++) acc[mi][ni][j] = 0.f;

    uint4 ra[4], rb[B_IT];

#define CLOAD(CC) { \
        const int k_  = (CC)/NCB, cb_ = (CC) - k_*NCB; \
        const int ky_ = k_/3 - 1, kx_ = k_%3 - 1; \
        const int hh_ = h + ky_; \
        const bool rok_ = (hh_ >= 0) && (hh_ < K_H); \
        const uint32_t* ab_ = act + ((size_t)(b*K_H + (rok_?hh_:0))*K_W)*Cin + cb_*32; \
        _Pragma("unroll") \
        for (int it = 0; it < 4; it++){ \
            int idx_ = it*256 + tid, px_ = idx_ >> 3, q_ = idx_ & 7; \
            int sx_ = px_ + kx_; \
            if (rok_ && sx_ >= 0 && sx_ < K_W) \
                ra[it] = *(const uint4*)(ab_ + (size_t)sx_*Cin + q_*4); \
            else ra[it] = make_uint4(0u,0u,0u,0u); \
        } \
        const uint32_t* bb_ = wp + ((size_t)(k_*Cout + cob))*Cin + cb_*32; \
        _Pragma("unroll") \
        for (int it = 0; it < B_IT; it++){ \
            int idx_ = it*256 + tid, r_ = idx_ >> 3, q_ = idx_ & 7; \
            rb[it] = *(const uint4*)(bb_ + (size_t)r_*Cin + q_*4); \
        } }

#define CSTORE(BI) { \
        const uint32_t aH_ = sbase + (BI)*BUF; \
        const uint32_t bH_ = aH_ + 2*ASZ; \
        _Pragma("unroll") \
        for (int it = 0; it < 4; it++){ \
            int idx_ = it*256 + tid, px_ = idx_ >> 3, q_ = idx_ & 7; \
            uint32_t off_ = (uint32_t)(px_*80 + q_*8); \
            sts64(aH_ + off_,       __byte_perm(ra[it].x, ra[it].y, 0x5410), __byte_perm(ra[it].z, ra[it].w, 0x5410)); \
            sts64(aH_ + ASZ + off_, __byte_perm(ra[it].x, ra[it].y, 0x7632), __byte_perm(ra[it].z, ra[it].w, 0x7632)); \
        } \
        _Pragma("unroll") \
        for (int it = 0; it < B_IT; it++){ \
            int idx_ = it*256 + tid, r_ = idx_ >> 3, q_ = idx_ & 7; \
            uint32_t off_ = (uint32_t)(r_*80 + q_*8); \
            sts64(bH_ + off_,       __byte_perm(rb[it].x, rb[it].y, 0x5410), __byte_perm(rb[it].z, rb[it].w, 0x5410)); \
            sts64(bH_ + BSZ + off_, __byte_perm(rb[it].x, rb[it].y, 0x7632), __byte_perm(rb[it].z, rb[it].w, 0x7632)); \
        } }

    // fragment base offsets (within a plane)
    const uint32_t aoff = (uint32_t)((wm*32 + (lane & 15))*80 + (lane >> 4)*16);
    const uint32_t boff = (uint32_t)((wn*(BN/2) + (lane & 15))*80 + (lane >> 4)*16);

    CLOAD(0);
    CSTORE(0);
    __syncthreads();

    int buf = 0;
    #pragma unroll 1
    for (int cc = 0; cc < NC; ++cc){
        if (cc + 1 < NC) CLOAD(cc + 1);

        const uint32_t aH = sbase + buf*BUF;
        const uint32_t bH = aH + 2*ASZ;
        #pragma unroll
        for (int ks = 0; ks < 2; ks++){
            uint32_t ah[2][4], al[2][4];
            #pragma unroll
            for (int mi = 0; mi < 2; mi++){
                ldsm4(ah[mi], aH       + aoff + mi*1280 + ks*32);
                ldsm4(al[mi], aH + ASZ + aoff + mi*1280 + ks*32);
            }
            #pragma unroll
            for (int nj = 0; nj < NI/2; nj++){
                uint32_t bh[4], bl[4];
                ldsm4(bh, bH       + boff + nj*1280 + ks*32);
                ldsm4(bl, bH + BSZ + boff + nj*1280 + ks*32);
                #pragma unroll
                for (int mi = 0; mi < 2; mi++){
                    mma16816(acc[mi][2*nj],   ah[mi], bh[0], bh[2]);
                    mma16816(acc[mi][2*nj],   ah[mi], bl[0], bl[2]);
                    mma16816(acc[mi][2*nj],   al[mi], bh[0], bh[2]);
                    mma16816(acc[mi][2*nj+1], ah[mi], bh[1], bh[3]);
                    mma16816(acc[mi][2*nj+1], ah[mi], bl[1], bl[3]);
                    mma16816(acc[mi][2*nj+1], al[mi], bh[1], bh[3]);
                }
            }
        }

        if (cc + 1 < NC){
            __syncthreads();
            CSTORE(buf ^ 1);
            __syncthreads();
            buf ^= 1;
        }
    }
#undef CLOAD
#undef CSTORE

    // epilogue: +bias -> fp32 NHWC
    float* base = out + ((size_t)(b*K_H + h)*K_W)*Cout;
    #pragma unroll
    for (int mi = 0; mi < 2; mi++){
        int px = wm*32 + mi*16 + (lane >> 2);
        #pragma unroll
        for (int ni = 0; ni < NI; ni++){
            int co = cob + wn*(BN/2) + ni*8 + (lane & 3)*2;
            float bv0 = __ldg(bias + co), bv1 = __ldg(bias + co + 1);
            float2 v0 = make_float2(acc[mi][ni][0] + bv0, acc[mi][ni][1] + bv1);
            float2 v1 = make_float2(acc[mi][ni][2] + bv0, acc[mi][ni][3] + bv1);
            *(float2*)(base + (size_t)px*Cout + co)       = v0;
            *(float2*)(base + (size_t)(px+8)*Cout + co)   = v1;
        }
    }
}

// ======================= GroupNorm =======================
template<int LAYER>
__global__ void gn_stats(){
    constexpr int C  = (LAYER==1)?256:(LAYER==2)?128:64;
    constexpr int Cg = (LAYER==3)?16:32;
    constexpr int G  = C/Cg;
    const float* y = (LAYER==1)?g_y1:(LAYER==2)?g_y2:g_y3;
    int bh = blockIdx.x;
    int b = bh >> 7;
    __shared__ float ss[8], sq[8];
    int tid = threadIdx.x;
    if (tid < G){ ss[tid] = 0.f; sq[tid] = 0.f; }
    __syncthreads();
    for (int c = tid; c < C; c += 256){
        float s = 0.f, q = 0.f;
        const float* p = y + (size_t)bh*K_W*C + c;
        #pragma unroll 4
        for (int px = 0; px < K_W; px++){
            float v = p[(size_t)px*C];
            s += v; q = fmaf(v, v, q);
        }
        atomicAdd(&ss[c/Cg], s);
        atomicAdd(&sq[c/Cg], q);
    }
    __syncthreads();
    if (tid < G){
        atomicAdd(&g_gs[LAYER-1][b*G + tid], ss[tid]);
        atomicAdd(&g_gq[LAYER-1][b*G + tid], sq[tid]);
    }
}

template<int LAYER>
__global__ void gn_fin(const float* __restrict__ gamma, const float* __restrict__ beta){
    constexpr int C  = (LAYER==1)?256:(LAYER==2)?128:64;
    constexpr int Cg = (LAYER==3)?16:32;
    float* sct = (LAYER==1)?g_sct1:(LAYER==2)?g_sct2:g_sct3;
    int i = blockIdx.x*blockDim.x + threadIdx.x;
    if (i >= K_B*C) return;
    int b = i / C, c = i % C;
    int g = b*(C/Cg) + c/Cg;
    float n   = (float)Cg * (float)K_HW;
    float mu  = g_gs[LAYER-1][g] / n;
    float var = g_gq[LAYER-1][g] / n - mu*mu;
    float inv = rsqrtf(var + 1e-5f);
    float s = gamma[c]*inv;
    sct[2*i]   = s;
    sct[2*i+1] = beta[c] - mu*s;
}

// ======================= segment pooling (GN3+relu fused) =======================
__global__ void pool_seg(const int* __restrict__ masks){
    __shared__ float sacc[K_NS][64];
    __shared__ float scnt[K_NS];
    int bh = blockIdx.x;
    int b = bh >> 7;
    int tid = threadIdx.x;
    for (int i = tid; i < K_NS*64; i += 256) (&sacc[0][0])[i] = 0.f;
    if (tid < K_NS) scnt[tid] = 0.f;
    __syncthreads();

    int c = tid & 63, g = tid >> 6;
    float2 st = ((const float2*)g_sct3)[b*64 + c];
    const float* yb = g_y3 + (size_t)bh*K_W*64;
    const int* mrow = masks + (size_t)bh*K_W;
    for (int px = g; px < K_W; px += 4){
        int seg = mrow[px];
        float v = fmaxf(fmaf(st.x, yb[(size_t)px*64 + c], st.y), 0.f);
        atomicAdd(&sacc[seg][c], v);
        if (c == 0) atomicAdd(&scnt[seg], 1.f);
    }
    __syncthreads();
    for (int i = tid; i < K_NS*64; i += 256) atomicAdd(&g_psum[b*K_NS*64 + i], (&sacc[0][0])[i]);
    if (tid < K_NS) atomicAdd(&g_pcnt[b*K_NS + tid], scnt[tid]);
}

// ======================= heads =======================
__global__ void heads(const float* __restrict__ wbox, const float* __restrict__ bbox,
                      const float* __restrict__ wconf, const float* __restrict__ bconf,
                      float* __restrict__ outp){
    int t = threadIdx.x;
    if (t >= K_B*32) return;
    int b = t / 32, o = t % 32, s = o + 1;
    float inv = 1.f / fmaxf(g_pcnt[b*K_NS + s], 1e-4f);
    const float* ps = &g_psum[(b*K_NS + s)*64];
    float pooled[64];
    #pragma unroll
    for (int c = 0; c < 64; c++) pooled[c] = ps[c]*inv;
    #pragma unroll
    for (int k = 0; k < 7; k++){
        float d = bbox[k];
        #pragma unroll
        for (int c = 0; c < 64; c++) d = fmaf(pooled[c], wbox[k*64+c], d);
        outp[(b*32 + o)*7 + k] = d;
    }
    float d = bconf[0];
    #pragma unroll
    for (int c = 0; c < 64; c++) d = fmaf(pooled[c], wconf[c], d);
    outp[K_B*32*7 + b*32 + o] = d;
}

// ======================= launch =======================
extern "C" void kernel_launch(void* const* d_in, const int* in_sizes, int n_in,
                              void* d_out, int out_size){
    const float* x      = (const float*)d_in[0];
    const int*   masks  = (const int*)  d_in[1];
    const float* wcoord = (const float*)d_in[2];
    const float* bcoord = (const float*)d_in[3];
    const float* w1     = (const float*)d_in[4];
    const float* b1     = (const float*)d_in[5];
    const float* gm1    = (const float*)d_in[6];
    const float* bt1    = (const float*)d_in[7];
    const float* w2     = (const float*)d_in[8];
    const float* b2     = (const float*)d_in[9];
    const float* gm2    = (const float*)d_in[10];
    const float* bt2    = (const float*)d_in[11];
    const float* w3     = (const float*)d_in[12];
    const float* b3     = (const float*)d_in[13];
    const float* gm3    = (const float*)d_in[14];
    const float* bt3    = (const float*)d_in[15];
    const float* wbox   = (const float*)d_in[16];
    const float* bbox   = (const float*)d_in[17];
    const float* wconf  = (const float*)d_in[18];
    const float* bconf  = (const float*)d_in[19];
    float* outp = (float*)d_out;

    const int SM1 = 2*(2*128*80 + 2*128*80);   // 81920
    const int SM2 = SM1;                        // BN=128
    const int SM3 = 2*(2*128*80 + 2*64*80);    // 61440
    cudaFuncSetAttribute(conv_hmma<1>, cudaFuncAttributeMaxDynamicSharedMemorySize, SM1);
    cudaFuncSetAttribute(conv_hmma<2>, cudaFuncAttributeMaxDynamicSharedMemorySize, SM2);
    cudaFuncSetAttribute(conv_hmma<3>, cudaFuncAttributeMaxDynamicSharedMemorySize, SM3);

    zero_bufs<<<33,256>>>();
    repack_w<1><<<512,256>>>(w1);
    repack_w<2><<<256,256>>>(w2);
    repack_w<3><<<128,256>>>(w3);
    { dim3 g(9, K_H, K_B); xform1<<<g,256>>>(x, wcoord, bcoord); }

    { dim3 g(K_H, K_B, 2); conv_hmma<1><<<g,256,SM1>>>(b1); }
    gn_stats<1><<<K_B*K_H,256>>>();
    gn_fin<1><<<(K_B*256+255)/256,256>>>(gm1, bt1);
    act_xform<2><<<(int)(((size_t)K_B*K_HW*256)/256),256>>>();

    { dim3 g(K_H, K_B, 1); conv_hmma<2><<<g,256,SM2>>>(b2); }
    gn_stats<2><<<K_B*K_H,256>>>();
    gn_fin<2><<<(K_B*128+255)/256,256>>>(gm2, bt2);
    act_xform<3><<<(int)(((size_t)K_B*K_HW*128)/256),256>>>();

    { dim3 g(K_H, K_B, 1); conv_hmma<3><<<g,256,SM3>>>(b3); }
    gn_stats<3><<<K_B*K_H,256>>>();
    gn_fin<3><<<1,256>>>(gm3, bt3);

    pool_seg<<<K_B*K_H,256>>>(masks);
    heads<<<1,128>>>(wbox, bbox, wconf, bconf, outp);
}

// round 4
// speedup vs baseline: 2.8404x; 1.1790x over previous
#include <cuda_runtime.h>
#include <cuda_bf16.h>
#include <cstdint>

#define K_H  128
#define K_W  128
#define K_HW 16384
#define K_B  4
#define K_NS 33

// ======================= device scratch (static, no alloc) =======================
// activations: separate bf16 hi / lo planes, NHWC
__device__ __align__(16) __nv_bfloat16 g_a1h[(size_t)K_B*K_HW*576];
__device__ __align__(16) __nv_bfloat16 g_a1l[(size_t)K_B*K_HW*576];
__device__ __align__(16) __nv_bfloat16 g_a2h[(size_t)K_B*K_HW*256];
__device__ __align__(16) __nv_bfloat16 g_a2l[(size_t)K_B*K_HW*256];
__device__ __align__(16) __nv_bfloat16 g_a3h[(size_t)K_B*K_HW*128];
__device__ __align__(16) __nv_bfloat16 g_a3l[(size_t)K_B*K_HW*128];
// conv outputs fp32 NHWC (pre-GN)
__device__ __align__(16) float g_y1[(size_t)K_B*K_HW*256];
__device__ __align__(16) float g_y2[(size_t)K_B*K_HW*128];
__device__ __align__(16) float g_y3[(size_t)K_B*K_HW*64];
// weights [k][co][ci] bf16 hi/lo planes
__device__ __align__(16) __nv_bfloat16 g_w1h[9*256*576];
__device__ __align__(16) __nv_bfloat16 g_w1l[9*256*576];
__device__ __align__(16) __nv_bfloat16 g_w2h[9*128*256];
__device__ __align__(16) __nv_bfloat16 g_w2l[9*128*256];
__device__ __align__(16) __nv_bfloat16 g_w3h[9*64*128];
__device__ __align__(16) __nv_bfloat16 g_w3l[9*64*128];
__device__ float g_gs[3][64], g_gq[3][64];
__device__ float g_sct1[K_B*256*2], g_sct2[K_B*128*2], g_sct3[K_B*64*2];
__device__ float g_psum[K_B*K_NS*64];
__device__ float g_pcnt[K_B*K_NS];

// ======================= helpers =======================
__device__ __forceinline__ uint32_t smem_u32(const void* p) {
    uint32_t a;
    asm("{ .reg .u64 t; cvta.to.shared.u64 t, %1; cvt.u32.u64 %0, t; }" : "=r"(a) : "l"(p));
    return a;
}
__device__ __forceinline__ void cp16(uint32_t dst, const void* src, uint32_t sz){
    asm volatile("cp.async.cg.shared.global [%0], [%1], 16, %2;" :: "r"(dst), "l"(src), "r"(sz));
}
#define CP_COMMIT() asm volatile("cp.async.commit_group;" ::: "memory")
#define CP_WAIT1()  asm volatile("cp.async.wait_group 1;"  ::: "memory")
__device__ __forceinline__ void ldsm4(uint32_t (&r)[4], uint32_t a){
    asm volatile("ldmatrix.sync.aligned.m8n8.x4.shared.b16 {%0,%1,%2,%3}, [%4];"
        : "=r"(r[0]), "=r"(r[1]), "=r"(r[2]), "=r"(r[3]) : "r"(a));
}
__device__ __forceinline__ void mma16816(float (&d)[4], const uint32_t (&a)[4],
                                         uint32_t b0, uint32_t b1){
    asm volatile(
        "mma.sync.aligned.m16n8k16.row.col.f32.bf16.bf16.f32 "
        "{%0,%1,%2,%3},{%4,%5,%6,%7},{%8,%9},{%0,%1,%2,%3};"
        : "+f"(d[0]), "+f"(d[1]), "+f"(d[2]), "+f"(d[3])
        : "r"(a[0]), "r"(a[1]), "r"(a[2]), "r"(a[3]), "r"(b0), "r"(b1));
}
__device__ __forceinline__ void split_hl(float v, __nv_bfloat16& h, __nv_bfloat16& l){
    h = __float2bfloat16(v);
    l = __float2bfloat16(v - __bfloat162float(h));
}

// ======================= small kernels =======================
__global__ void zero_bufs(){
    int i = blockIdx.x*256 + threadIdx.x;
    if (i < K_B*K_NS*64) g_psum[i] = 0.f;
    if (i < K_B*K_NS)    g_pcnt[i] = 0.f;
    if (i < 64){
        g_gs[0][i]=0.f; g_gs[1][i]=0.f; g_gs[2][i]=0.f;
        g_gq[0][i]=0.f; g_gq[1][i]=0.f; g_gq[2][i]=0.f;
    }
}

template<int LAYER>
__global__ void repack_w(const float* __restrict__ w){
    constexpr int Cin  = (LAYER==1)?576:(LAYER==2)?256:128;
    constexpr int Cout = (LAYER==1)?256:(LAYER==2)?128:64;
    __nv_bfloat16* wh = (LAYER==1)?g_w1h:(LAYER==2)?g_w2h:g_w3h;
    __nv_bfloat16* wl = (LAYER==1)?g_w1l:(LAYER==2)?g_w2l:g_w3l;
    int n = Cout*Cin*9;
    for (int i = blockIdx.x*blockDim.x + threadIdx.x; i < n; i += gridDim.x*blockDim.x){
        int k  = i % 9;
        int t  = i / 9;
        int ci = t % Cin;
        int co = t / Cin;
        __nv_bfloat16 h, l;
        split_hl(w[i], h, l);
        size_t o = ((size_t)k*Cout + co)*Cin + ci;
        wh[o] = h; wl[o] = l;
    }
}

// conv1 input: NCHW fp32 (+ computed coord feats 512..575) -> NHWC bf16 hi/lo planes
__global__ void xform1(const float* __restrict__ x, const float* __restrict__ wc,
                       const float* __restrict__ bc){
    __shared__ float tile[64][129];
    int cblk = blockIdx.x, h = blockIdx.y, b = blockIdx.z, tid = threadIdx.x;
    if (cblk < 8){
        for (int i = tid; i < 64*128; i += 256){
            int ci = i >> 7, w = i & 127;
            tile[ci][w] = x[(((size_t)b*512 + cblk*64 + ci)*K_H + h)*K_W + w];
        }
    } else {
        for (int i = tid; i < 64*128; i += 256){
            int ci = i >> 7, w = i & 127;
            tile[ci][w] = fmaxf(wc[2*ci]*(float)w + wc[2*ci+1]*(float)h + bc[ci], 0.f);
        }
    }
    __syncthreads();
    for (int i = tid; i < 64*128; i += 256){
        int px = i >> 6, c = i & 63;
        __nv_bfloat16 hv, lv;
        split_hl(tile[c][px], hv, lv);
        size_t o = (((size_t)b*K_H + h)*K_W + px)*576 + cblk*64 + c;
        g_a1h[o] = hv; g_a1l[o] = lv;
    }
}

// GN apply + relu + split (fp32 NHWC -> bf16 hi/lo NHWC)
template<int L>
__global__ void act_xform(){
    constexpr int C = (L==2)?256:128;
    const float* __restrict__ y   = (L==2)?g_y1:g_y2;
    const float* __restrict__ sct = (L==2)?g_sct1:g_sct2;
    __nv_bfloat16* __restrict__ ah = (L==2)?g_a2h:g_a3h;
    __nv_bfloat16* __restrict__ al = (L==2)?g_a2l:g_a3l;
    size_t idx = (size_t)blockIdx.x*256 + threadIdx.x;
    if (idx >= (size_t)K_B*K_HW*C) return;
    int c = (int)(idx % C);
    int b = (int)(idx / ((size_t)K_HW*C));
    float2 st = ((const float2*)sct)[b*C + c];
    float v = fmaxf(fmaf(st.x, y[idx], st.y), 0.f);
    __nv_bfloat16 hv, lv;
    split_hl(v, hv, lv);
    ah[idx] = hv; al[idx] = lv;
}

// ======================= conv3x3 via mma.sync bf16x3 + cp.async =======================
// CTA: M=128 px (one row) x N=BN co; 8 warps 4(M)x2(N); warp tile 32 x BN/2.
// chunk cc over (ky, cb, kx): A tile (130 rows incl. zero guards) shared across 3 kx.
// A: 2-deep ring, B: 3-deep ring (buf = kx), cp.async double-buffered, 1 sync/chunk.
template<int LAYER>
__global__ void __launch_bounds__(256,2)
conv_hmma(const float* __restrict__ bias){
    constexpr int Cin  = (LAYER==1)?576:(LAYER==2)?256:128;
    constexpr int Cout = (LAYER==1)?256:(LAYER==2)?128:64;
    constexpr int BN   = (Cout>=128)?128:64;
    constexpr int NCB  = Cin/32;          // K-chunks of 32 per kernel tap
    constexpr int NC   = 9*NCB;           // total chunks
    constexpr int NI   = BN/16;
    constexpr int BIT  = BN/64;           // B cp.async iters (2 or 1)
    constexpr int APL  = 10496;           // A plane stride (130 rows * 80B, padded)
    constexpr int BPL  = BN*80;           // B plane bytes
    constexpr int ABYT = 4*APL;           // 2 bufs * 2 planes

    const __nv_bfloat16* __restrict__ act_h = (LAYER==1)?g_a1h:(LAYER==2)?g_a2h:g_a3h;
    const __nv_bfloat16* __restrict__ act_l = (LAYER==1)?g_a1l:(LAYER==2)?g_a2l:g_a3l;
    const __nv_bfloat16* __restrict__ w_h   = (LAYER==1)?g_w1h:(LAYER==2)?g_w2h:g_w3h;
    const __nv_bfloat16* __restrict__ w_l   = (LAYER==1)?g_w1l:(LAYER==2)?g_w2l:g_w3l;
    float* __restrict__ out = (LAYER==1)?g_y1:(LAYER==2)?g_y2:g_y3;

    extern __shared__ __align__(128) char dsm[];
    const uint32_t sbase = smem_u32(dsm);

    const int tid  = threadIdx.x;
    const int lane = tid & 31;
    const int wm   = (tid >> 5) & 3;
    const int wn   = tid >> 7;
    const int h    = blockIdx.x;
    const int b    = blockIdx.y;
    const int cob  = blockIdx.z*BN;

    // zero guard rows (px=-1, px=128) in all 4 A planes; never overwritten.
    if (tid < 160){
        int pl = tid/40, rem = tid%40;
        uint32_t row = (rem >= 20) ? 129u : 0u;
        *(uint32_t*)(dsm + pl*APL + row*80 + (rem%20)*4) = 0u;
    }

    float acc[2][NI][4];
    #pragma unroll
    for (int mi=0;mi<2;mi++)
        #pragma unroll
        for (int ni=0;ni<NI;ni++)
            #pragma unroll
            for (int j=0;j<4;j++) acc[mi][ni][j] = 0.f;

#define ALOAD(G) { \
        const int g_ = (G); \
        const int ky_ = g_/NCB, cbk_ = g_ - ky_*NCB; \
        const int hh_ = h + ky_ - 1; \
        const uint32_t sz_ = (hh_>=0 && hh_<K_H) ? 16u : 0u; \
        const int hc_ = hh_<0?0:(hh_>127?127:hh_); \
        const size_t so_ = ((size_t)(b*K_H + hc_)*K_W)*Cin + cbk_*32; \
        const __nv_bfloat16* sh_ = act_h + so_; \
        const __nv_bfloat16* sl_ = act_l + so_; \
        const uint32_t db_ = sbase + (uint32_t)((g_&1)*2)*APL; \
        _Pragma("unroll") \
        for (int it = 0; it < 2; it++){ \
            int idx_ = it*256 + tid, r_ = idx_>>2, q_ = idx_&3; \
            uint32_t d_ = db_ + (r_+1)*80 + q_*16; \
            const size_t off_ = (size_t)r_*Cin + q_*8; \
            cp16(d_,        sh_ + off_, sz_); \
            cp16(d_ + APL,  sl_ + off_, sz_); \
        } }

#define BLOAD(CC) { \
        const int cc_ = (CC); \
        const int g_ = cc_/3, kx_ = cc_ - g_*3; \
        const int k_ = (g_/NCB)*3 + kx_, cbk_ = g_%NCB; \
        const size_t so_ = ((size_t)(k_*Cout + cob))*Cin + cbk_*32; \
        const __nv_bfloat16* sh_ = w_h + so_; \
        const __nv_bfloat16* sl_ = w_l + so_; \
        const uint32_t db_ = sbase + ABYT + (uint32_t)(kx_*2)*BPL; \
        _Pragma("unroll") \
        for (int it = 0; it < BIT; it++){ \
            int idx_ = it*256 + tid, r_ = idx_>>2, q_ = idx_&3; \
            uint32_t d_ = db_ + r_*80 + q_*16; \
            const size_t off_ = (size_t)r_*Cin + q_*8; \
            cp16(d_,        sh_ + off_, 16u); \
            cp16(d_ + BPL,  sl_ + off_, 16u); \
        } }

    const uint32_t aoff0 = (uint32_t)((wm*32 + (lane & 15))*80 + (lane >> 4)*16);
    const uint32_t boff  = (uint32_t)((wn*(BN/2) + (lane & 15))*80 + (lane >> 4)*16);

    // prologue: G0 = A(0)+B(0), G1 = B(1)
    ALOAD(0); BLOAD(0); CP_COMMIT();
    BLOAD(1); CP_COMMIT();

    #pragma unroll 1
    for (int cc = 0; cc < NC; ++cc){
        const int g  = cc/3;
        const int kx = cc - g*3;
        CP_WAIT1();           // groups <= cc complete
        __syncthreads();      // publish + all warps done with chunk cc-1

        const uint32_t Ab = sbase + (uint32_t)((g&1)*2)*APL;
        const uint32_t Bb = sbase + ABYT + (uint32_t)(kx*2)*BPL;
        const uint32_t ao = aoff0 + (uint32_t)((kx)*80);   // row px+kx-1+1 = px+kx ... guard at row0

        #pragma unroll
        for (int ks = 0; ks < 2; ks++){
            uint32_t ah[2][4], al[2][4];
            #pragma unroll
            for (int mi = 0; mi < 2; mi++){
                ldsm4(ah[mi], Ab       + ao + mi*1280 + ks*32);
                ldsm4(al[mi], Ab + APL + ao + mi*1280 + ks*32);
            }
            #pragma unroll
            for (int nj = 0; nj < NI/2; nj++){
                uint32_t bh[4], bl[4];
                ldsm4(bh, Bb       + boff + nj*1280 + ks*32);
                ldsm4(bl, Bb + BPL + boff + nj*1280 + ks*32);
                #pragma unroll
                for (int mi = 0; mi < 2; mi++){
                    mma16816(acc[mi][2*nj],   ah[mi], bh[0], bh[2]);
                    mma16816(acc[mi][2*nj],   ah[mi], bl[0], bl[2]);
                    mma16816(acc[mi][2*nj],   al[mi], bh[0], bh[2]);
                    mma16816(acc[mi][2*nj+1], ah[mi], bh[1], bh[3]);
                    mma16816(acc[mi][2*nj+1], ah[mi], bl[1], bl[3]);
                    mma16816(acc[mi][2*nj+1], al[mi], bh[1], bh[3]);
                }
            }
        }

        // issue loads for chunk cc+2 (B ring slot (cc+2)%3; A when entering new group)
        if (cc + 2 < NC){
            BLOAD(cc + 2);
            if ((cc + 2) % 3 == 0) ALOAD((cc + 2)/3);
        }
        CP_COMMIT();
    }
#undef ALOAD
#undef BLOAD

    // epilogue: +bias -> fp32 NHWC
    float* base = out + ((size_t)(b*K_H + h)*K_W)*Cout;
    #pragma unroll
    for (int mi = 0; mi < 2; mi++){
        int px = wm*32 + mi*16 + (lane >> 2);
        #pragma unroll
        for (int ni = 0; ni < NI; ni++){
            int co = cob + wn*(BN/2) + ni*8 + (lane & 3)*2;
            float bv0 = __ldg(bias + co), bv1 = __ldg(bias + co + 1);
            float2 v0 = make_float2(acc[mi][ni][0] + bv0, acc[mi][ni][1] + bv1);
            float2 v1 = make_float2(acc[mi][ni][2] + bv0, acc[mi][ni][3] + bv1);
            *(float2*)(base + (size_t)px*Cout + co)     = v0;
            *(float2*)(base + (size_t)(px+8)*Cout + co) = v1;
        }
    }
}

// ======================= GroupNorm =======================
template<int LAYER>
__global__ void gn_stats(){
    constexpr int C  = (LAYER==1)?256:(LAYER==2)?128:64;
    constexpr int Cg = (LAYER==3)?16:32;
    constexpr int G  = C/Cg;
    const float* y = (LAYER==1)?g_y1:(LAYER==2)?g_y2:g_y3;
    int bh = blockIdx.x;
    int b = bh >> 7;
    __shared__ float ss[8], sq[8];
    int tid = threadIdx.x;
    if (tid < G){ ss[tid] = 0.f; sq[tid] = 0.f; }
    __syncthreads();
    for (int c = tid; c < C; c += 256){
        float s = 0.f, q = 0.f;
        const float* p = y + (size_t)bh*K_W*C + c;
        #pragma unroll 4
        for (int px = 0; px < K_W; px++){
            float v = p[(size_t)px*C];
            s += v; q = fmaf(v, v, q);
        }
        atomicAdd(&ss[c/Cg], s);
        atomicAdd(&sq[c/Cg], q);
    }
    __syncthreads();
    if (tid < G){
        atomicAdd(&g_gs[LAYER-1][b*G + tid], ss[tid]);
        atomicAdd(&g_gq[LAYER-1][b*G + tid], sq[tid]);
    }
}

template<int LAYER>
__global__ void gn_fin(const float* __restrict__ gamma, const float* __restrict__ beta){
    constexpr int C  = (LAYER==1)?256:(LAYER==2)?128:64;
    constexpr int Cg = (LAYER==3)?16:32;
    float* sct = (LAYER==1)?g_sct1:(LAYER==2)?g_sct2:g_sct3;
    int i = blockIdx.x*blockDim.x + threadIdx.x;
    if (i >= K_B*C) return;
    int b = i / C, c = i % C;
    int g = b*(C/Cg) + c/Cg;
    float n   = (float)Cg * (float)K_HW;
    float mu  = g_gs[LAYER-1][g] / n;
    float var = g_gq[LAYER-1][g] / n - mu*mu;
    float inv = rsqrtf(var + 1e-5f);
    float s = gamma[c]*inv;
    sct[2*i]   = s;
    sct[2*i+1] = beta[c] - mu*s;
}

// ======================= segment pooling (GN3+relu fused) =======================
__global__ void pool_seg(const int* __restrict__ masks){
    __shared__ float sacc[K_NS][64];
    __shared__ float scnt[K_NS];
    int bh = blockIdx.x;
    int b = bh >> 7;
    int tid = threadIdx.x;
    for (int i = tid; i < K_NS*64; i += 256) (&sacc[0][0])[i] = 0.f;
    if (tid < K_NS) scnt[tid] = 0.f;
    __syncthreads();

    int c = tid & 63, g = tid >> 6;
    float2 st = ((const float2*)g_sct3)[b*64 + c];
    const float* yb = g_y3 + (size_t)bh*K_W*64;
    const int* mrow = masks + (size_t)bh*K_W;
    for (int px = g; px < K_W; px += 4){
        int seg = mrow[px];
        float v = fmaxf(fmaf(st.x, yb[(size_t)px*64 + c], st.y), 0.f);
        atomicAdd(&sacc[seg][c], v);
        if (c == 0) atomicAdd(&scnt[seg], 1.f);
    }
    __syncthreads();
    for (int i = tid; i < K_NS*64; i += 256) atomicAdd(&g_psum[b*K_NS*64 + i], (&sacc[0][0])[i]);
    if (tid < K_NS) atomicAdd(&g_pcnt[b*K_NS + tid], scnt[tid]);
}

// ======================= heads =======================
__global__ void heads(const float* __restrict__ wbox, const float* __restrict__ bbox,
                      const float* __restrict__ wconf, const float* __restrict__ bconf,
                      float* __restrict__ outp){
    int t = threadIdx.x;
    if (t >= K_B*32) return;
    int b = t / 32, o = t % 32, s = o + 1;
    float inv = 1.f / fmaxf(g_pcnt[b*K_NS + s], 1e-4f);
    const float* ps = &g_psum[(b*K_NS + s)*64];
    float pooled[64];
    #pragma unroll
    for (int c = 0; c < 64; c++) pooled[c] = ps[c]*inv;
    #pragma unroll
    for (int k = 0; k < 7; k++){
        float d = bbox[k];
        #pragma unroll
        for (int c = 0; c < 64; c++) d = fmaf(pooled[c], wbox[k*64+c], d);
        outp[(b*32 + o)*7 + k] = d;
    }
    float d = bconf[0];
    #pragma unroll
    for (int c = 0; c < 64; c++) d = fmaf(pooled[c], wconf[c], d);
    outp[K_B*32*7 + b*32 + o] = d;
}

// ======================= launch =======================
extern "C" void kernel_launch(void* const* d_in, const int* in_sizes, int n_in,
                              void* d_out, int out_size){
    const float* x      = (const float*)d_in[0];
    const int*   masks  = (const int*)  d_in[1];
    const float* wcoord = (const float*)d_in[2];
    const float* bcoord = (const float*)d_in[3];
    const float* w1     = (const float*)d_in[4];
    const float* b1     = (const float*)d_in[5];
    const float* gm1    = (const float*)d_in[6];
    const float* bt1    = (const float*)d_in[7];
    const float* w2     = (const float*)d_in[8];
    const float* b2     = (const float*)d_in[9];
    const float* gm2    = (const float*)d_in[10];
    const float* bt2    = (const float*)d_in[11];
    const float* w3     = (const float*)d_in[12];
    const float* b3     = (const float*)d_in[13];
    const float* gm3    = (const float*)d_in[14];
    const float* bt3    = (const float*)d_in[15];
    const float* wbox   = (const float*)d_in[16];
    const float* bbox   = (const float*)d_in[17];
    const float* wconf  = (const float*)d_in[18];
    const float* bconf  = (const float*)d_in[19];
    float* outp = (float*)d_out;

    const int SM1 = 4*10496 + 6*128*80;   // 41984 + 61440 = 103424
    const int SM2 = SM1;
    const int SM3 = 4*10496 + 6*64*80;    // 41984 + 30720 = 72704
    cudaFuncSetAttribute(conv_hmma<1>, cudaFuncAttributeMaxDynamicSharedMemorySize, SM1);
    cudaFuncSetAttribute(conv_hmma<2>, cudaFuncAttributeMaxDynamicSharedMemorySize, SM2);
    cudaFuncSetAttribute(conv_hmma<3>, cudaFuncAttributeMaxDynamicSharedMemorySize, SM3);

    zero_bufs<<<33,256>>>();
    repack_w<1><<<512,256>>>(w1);
    repack_w<2><<<256,256>>>(w2);
    repack_w<3><<<128,256>>>(w3);
    { dim3 g(9, K_H, K_B); xform1<<<g,256>>>(x, wcoord, bcoord); }

    { dim3 g(K_H, K_B, 2); conv_hmma<1><<<g,256,SM1>>>(b1); }
    gn_stats<1><<<K_B*K_H,256>>>();
    gn_fin<1><<<(K_B*256+255)/256,256>>>(gm1, bt1);
    act_xform<2><<<(int)(((size_t)K_B*K_HW*256)/256),256>>>();

    { dim3 g(K_H, K_B, 1); conv_hmma<2><<<g,256,SM2>>>(b2); }
    gn_stats<2><<<K_B*K_H,256>>>();
    gn_fin<2><<<(K_B*128+255)/256,256>>>(gm2, bt2);
    act_xform<3><<<(int)(((size_t)K_B*K_HW*128)/256),256>>>();

    { dim3 g(K_H, K_B, 1); conv_hmma<3><<<g,256,SM3>>>(b3); }
    gn_stats<3><<<K_B*K_H,256>>>();
    gn_fin<3><<<1,256>>>(gm3, bt3);

    pool_seg<<<K_B*K_H,256>>>(masks);
    heads<<<1,128>>>(wbox, bbox, wconf, bconf, outp);
}